// round 4
// baseline (speedup 1.0000x reference)
#include <cuda_runtime.h>
#include <math.h>

// GCN: N=150000 nodes, E=2,000,000 edges, F=128 -> H=64 -> C=40
// edge_index arrives as int32 [2, E] (harness delivers int32; JAX x64 off).
// Pipeline:
//   deg/hist -> dinv -> exclusive scan -> CSR build (col-sorted)
//   GEMM1 (x@W1) -> agg1 (CSR gather + self-loop + b1 + ReLU)
//   GEMM2 (a1@W2) -> agg2 (CSR gather + self-loop + b2 + log_softmax) -> out

#define F_IN 128
#define F_H  64
#define F_C  40
#define MAXN 150016
#define MAXE 2000064

__device__ __align__(16) float g_deg[MAXN];
__device__ __align__(16) float g_dinv[MAXN];
__device__ __align__(16) int   g_hist[MAXN];
__device__ __align__(16) int   g_base[MAXN + 1];
__device__ __align__(16) int   g_cursor[MAXN];
__device__ __align__(16) int   g_erow[MAXE];
__device__ __align__(16) int   g_ecol[MAXE];
__device__ __align__(16) int   g_crow[MAXE];
__device__ __align__(16) float g_cw[MAXE];
__device__ __align__(16) float g_h1[MAXN * F_H];   // x @ W1
__device__ __align__(16) float g_a1[MAXN * F_H];   // relu(conv1)
__device__ __align__(16) float g_h2[MAXN * F_C];   // a1 @ W2

// ---------------------------------------------------------------------------
__global__ void k_zero(int N) {
    int i = blockIdx.x * blockDim.x + threadIdx.x;
    if (i < N) { g_deg[i] = 0.0f; g_hist[i] = 0; }
}

// degrees + per-column histogram; stash row/col (int32 input)
__global__ void k_deg(const int* __restrict__ ei,
                      const float* __restrict__ ew, int E, int N) {
    int e = blockIdx.x * blockDim.x + threadIdx.x;
    if (e >= E) return;
    int r = ei[e];
    int c = ei[E + e];
    g_erow[e] = r;
    g_ecol[e] = c;
    if ((unsigned)r < (unsigned)N && (unsigned)c < (unsigned)N) {
        atomicAdd(&g_deg[c], ew[e]);
        atomicAdd(&g_hist[c], 1);
    }
}

// deg includes self-loop weight 1 -> always > 0
__global__ void k_dinv(int N) {
    int i = blockIdx.x * blockDim.x + threadIdx.x;
    if (i < N) {
        float d = g_deg[i] + 1.0f;
        g_dinv[i] = rsqrtf(d);
    }
}

// single-block exclusive scan of g_hist -> g_base (and g_cursor copy)
__global__ void k_scan(int N) {
    __shared__ int wsum[32];
    __shared__ int s_carry, s_tot;
    int tid = threadIdx.x, lane = tid & 31, wid = tid >> 5;
    if (tid == 0) s_carry = 0;
    __syncthreads();
    for (int t0 = 0; t0 < N; t0 += 1024) {
        int i = t0 + tid;
        int v = (i < N) ? g_hist[i] : 0;
        int s = v;
        #pragma unroll
        for (int o = 1; o < 32; o <<= 1) {
            int n = __shfl_up_sync(0xffffffffu, s, o);
            if (lane >= o) s += n;
        }
        if (lane == 31) wsum[wid] = s;
        __syncthreads();
        if (wid == 0) {
            int w = wsum[lane];
            int ss = w;
            #pragma unroll
            for (int o = 1; o < 32; o <<= 1) {
                int n = __shfl_up_sync(0xffffffffu, ss, o);
                if (lane >= o) ss += n;
            }
            wsum[lane] = ss - w;            // exclusive warp offsets
            if (lane == 31) s_tot = ss;     // block total
        }
        __syncthreads();
        int excl = s_carry + wsum[wid] + (s - v);
        if (i < N) { g_base[i] = excl; g_cursor[i] = excl; }
        __syncthreads();
        if (tid == 0) s_carry += s_tot;
        __syncthreads();
    }
    if (tid == 0) g_base[N] = s_carry;
}

// scatter edges into column-sorted CSR; precompute normalized weight
__global__ void k_csr(const float* __restrict__ ew, int E, int N) {
    int e = blockIdx.x * blockDim.x + threadIdx.x;
    if (e >= E) return;
    int r = g_erow[e], c = g_ecol[e];
    if ((unsigned)r >= (unsigned)N || (unsigned)c >= (unsigned)N) return;
    int pos = atomicAdd(&g_cursor[c], 1);
    g_crow[pos] = r;
    g_cw[pos]   = g_dinv[r] * ew[e] * g_dinv[c];
}

// ---------------------------------------------------------------------------
// GEMM1: h1[N,64] = x[N,128] @ W1[128,64].  64-row tile, 2 K-chunks of 64.
__global__ void k_gemm1(const float* __restrict__ x,
                        const float* __restrict__ W1, int N) {
    __shared__ __align__(16) float xs[64][65];     // [r][k] padded
    __shared__ __align__(16) float Ws[64 * 64];    // [k][c] flat
    int tid  = threadIdx.x;          // 256
    int row0 = blockIdx.x * 64;
    int r0 = (tid & 15) * 4;
    int c0 = (tid >> 4) * 4;
    float acc[4][4];
    #pragma unroll
    for (int i = 0; i < 4; i++)
        #pragma unroll
        for (int j = 0; j < 4; j++) acc[i][j] = 0.0f;

    for (int kk = 0; kk < 128; kk += 64) {
        __syncthreads();
        // load W chunk: rows kk..kk+63 of [128,64] -> Ws[k*64+c]
        for (int i = tid; i < 1024; i += 256) {
            int k = i >> 4, cc = (i & 15) << 2;
            *(float4*)&Ws[k * 64 + cc] = *(const float4*)&W1[(size_t)(kk + k) * 64 + cc];
        }
        // load x tile chunk: xs[r][k]
        for (int i = tid; i < 1024; i += 256) {
            int r = i >> 4, kc = (i & 15) << 2;
            int row = row0 + r;
            float4 v = make_float4(0.f, 0.f, 0.f, 0.f);
            if (row < N) v = *(const float4*)&x[(size_t)row * 128 + kk + kc];
            xs[r][kc] = v.x; xs[r][kc + 1] = v.y; xs[r][kc + 2] = v.z; xs[r][kc + 3] = v.w;
        }
        __syncthreads();
        #pragma unroll
        for (int k = 0; k < 64; k++) {
            float a0 = xs[r0][k], a1 = xs[r0 + 1][k], a2 = xs[r0 + 2][k], a3 = xs[r0 + 3][k];
            float4 b = *(const float4*)&Ws[k * 64 + c0];
            acc[0][0] += a0 * b.x; acc[0][1] += a0 * b.y; acc[0][2] += a0 * b.z; acc[0][3] += a0 * b.w;
            acc[1][0] += a1 * b.x; acc[1][1] += a1 * b.y; acc[1][2] += a1 * b.z; acc[1][3] += a1 * b.w;
            acc[2][0] += a2 * b.x; acc[2][1] += a2 * b.y; acc[2][2] += a2 * b.z; acc[2][3] += a2 * b.w;
            acc[3][0] += a3 * b.x; acc[3][1] += a3 * b.y; acc[3][2] += a3 * b.z; acc[3][3] += a3 * b.w;
        }
    }
    #pragma unroll
    for (int i = 0; i < 4; i++) {
        int row = row0 + r0 + i;
        if (row < N)
            *(float4*)&g_h1[(size_t)row * 64 + c0] =
                make_float4(acc[i][0], acc[i][1], acc[i][2], acc[i][3]);
    }
}

// agg1: warp per node. acc = b1 + dinv^2*h1[self] + sum_e w*h1[src]; relu.
// 2-deep software pipeline on (row, weight) to raise MLP.
__global__ void k_agg1(const float* __restrict__ b1, int N) {
    int node = blockIdx.x * (blockDim.x >> 5) + (threadIdx.x >> 5);
    int lane = threadIdx.x & 31;
    if (node >= N) return;
    int s = g_base[node], e = g_base[node + 1];
    float di = g_dinv[node], d2 = di * di;
    const float* hr = &g_h1[(size_t)node * 64];
    float acc0 = b1[lane]      + d2 * hr[lane];
    float acc1 = b1[lane + 32] + d2 * hr[lane + 32];
    if (s < e) {
        int   r = g_crow[s];
        float w = g_cw[s];
        for (int j = s + 1; j < e; j++) {
            int   rn = g_crow[j];
            float wn = g_cw[j];
            const float* p = &g_h1[(size_t)r * 64];
            acc0 += w * p[lane];
            acc1 += w * p[lane + 32];
            r = rn; w = wn;
        }
        const float* p = &g_h1[(size_t)r * 64];
        acc0 += w * p[lane];
        acc1 += w * p[lane + 32];
    }
    g_a1[(size_t)node * 64 + lane]      = fmaxf(acc0, 0.0f);
    g_a1[(size_t)node * 64 + lane + 32] = fmaxf(acc1, 0.0f);
}

// GEMM2: h2[N,40] = a1[N,64] @ W2[64,40]
__global__ void k_gemm2(const float* __restrict__ W2, int N) {
    __shared__ __align__(16) float xs[64][65];
    __shared__ __align__(16) float Ws[64 * 40];
    int tid  = threadIdx.x;          // 256
    int row0 = blockIdx.x * 64;
    for (int i = tid; i < 64 * 40; i += 256) Ws[i] = W2[i];
    for (int i = tid; i < 1024; i += 256) {
        int r = i >> 4, kc = (i & 15) << 2;
        int row = row0 + r;
        float4 v = make_float4(0.f, 0.f, 0.f, 0.f);
        if (row < N) v = *(const float4*)&g_a1[(size_t)row * 64 + kc];
        xs[r][kc] = v.x; xs[r][kc + 1] = v.y; xs[r][kc + 2] = v.z; xs[r][kc + 3] = v.w;
    }
    __syncthreads();
    int r0 = (tid & 31) * 2;         // 64 rows
    int cg = (tid >> 5) * 5;         // 8 groups * 5 = 40 cols
    float acc[2][5];
    #pragma unroll
    for (int i = 0; i < 2; i++)
        #pragma unroll
        for (int j = 0; j < 5; j++) acc[i][j] = 0.0f;
    #pragma unroll
    for (int k = 0; k < 64; k++) {
        float a0 = xs[r0][k], a1 = xs[r0 + 1][k];
        #pragma unroll
        for (int j = 0; j < 5; j++) {
            float b = Ws[k * 40 + cg + j];
            acc[0][j] += a0 * b;
            acc[1][j] += a1 * b;
        }
    }
    #pragma unroll
    for (int i = 0; i < 2; i++) {
        int row = row0 + r0 + i;
        if (row < N) {
            #pragma unroll
            for (int j = 0; j < 5; j++)
                g_h2[(size_t)row * 40 + cg + j] = acc[i][j];
        }
    }
}

// agg2 + log_softmax: warp per node, 40 classes (lanes 0..31 + lanes 0..7 again)
__global__ void k_agg2(const float* __restrict__ b2, float* __restrict__ out, int N) {
    int node = blockIdx.x * (blockDim.x >> 5) + (threadIdx.x >> 5);
    int lane = threadIdx.x & 31;
    if (node >= N) return;
    int s = g_base[node], e = g_base[node + 1];
    float di = g_dinv[node], d2 = di * di;
    const float* hr = &g_h2[(size_t)node * 40];
    int i2 = 32 + (lane & 7);
    float acc0 = b2[lane] + d2 * hr[lane];
    float acc1 = b2[i2]   + d2 * hr[i2];
    if (s < e) {
        int   r = g_crow[s];
        float w = g_cw[s];
        for (int j = s + 1; j < e; j++) {
            int   rn = g_crow[j];
            float wn = g_cw[j];
            const float* p = &g_h2[(size_t)r * 40];
            acc0 += w * p[lane];
            acc1 += w * p[i2];
            r = rn; w = wn;
        }
        const float* p = &g_h2[(size_t)r * 40];
        acc0 += w * p[lane];
        acc1 += w * p[i2];
    }
    bool hi = lane < 8;
    float m = fmaxf(acc0, hi ? acc1 : -INFINITY);
    #pragma unroll
    for (int o = 16; o > 0; o >>= 1) m = fmaxf(m, __shfl_xor_sync(0xffffffffu, m, o));
    float sum = expf(acc0 - m) + (hi ? expf(acc1 - m) : 0.0f);
    #pragma unroll
    for (int o = 16; o > 0; o >>= 1) sum += __shfl_xor_sync(0xffffffffu, sum, o);
    float lse = m + logf(sum);
    out[(size_t)node * 40 + lane] = acc0 - lse;
    if (hi) out[(size_t)node * 40 + i2] = acc1 - lse;
}

// ---------------------------------------------------------------------------
extern "C" void kernel_launch(void* const* d_in, const int* in_sizes, int n_in,
                              void* d_out, int out_size) {
    const float* x  = (const float*)d_in[0];
    const int*   ei = (const int*)d_in[1];      // int32 [2, E]
    const float* ew = (const float*)d_in[2];
    const float* W1 = (const float*)d_in[3];
    const float* b1 = (const float*)d_in[4];
    const float* W2 = (const float*)d_in[5];
    const float* b2 = (const float*)d_in[6];
    float* out = (float*)d_out;

    int N = in_sizes[0] / F_IN;
    int E = in_sizes[2];

    k_zero <<<(N + 255) / 256, 256>>>(N);
    k_deg  <<<(E + 255) / 256, 256>>>(ei, ew, E, N);
    k_dinv <<<(N + 255) / 256, 256>>>(N);
    k_scan <<<1, 1024>>>(N);
    k_csr  <<<(E + 255) / 256, 256>>>(ew, E, N);
    k_gemm1<<<(N + 63) / 64, 256>>>(x, W1, N);
    k_agg1 <<<(N + 7) / 8, 256>>>(b1, N);
    k_gemm2<<<(N + 63) / 64, 256>>>(W2, N);
    k_agg2 <<<(N + 7) / 8, 256>>>(b2, out, N);
}

// round 5
// speedup vs baseline: 1.2418x; 1.2418x over previous
#include <cuda_runtime.h>
#include <math.h>

// GCN: N=150000 nodes, E=2,000,000 edges, F=128 -> H=64 -> C=40
// edge_index arrives as int32 [2, E].
// Pipeline:
//   deg/hist -> dinv -> 3-phase hierarchical scan -> CSR build (col-sorted)
//   GEMM1 (x@W1) -> agg1 (CSR gather + self-loop + b1 + ReLU)
//   GEMM2 (a1@W2) -> agg2 (CSR gather + self-loop + b2 + log_softmax) -> out

#define F_IN 128
#define F_H  64
#define F_C  40
#define MAXN 150016
#define MAXE 2000064
#define SCAN_TILE 1024
#define MAXB ((MAXN + SCAN_TILE - 1) / SCAN_TILE)

__device__ __align__(16) float g_deg[MAXN];
__device__ __align__(16) float g_dinv[MAXN];
__device__ __align__(16) int   g_hist[MAXN];
__device__ __align__(16) int   g_base[MAXN + 1];
__device__ __align__(16) int   g_cursor[MAXN];
__device__ __align__(16) int   g_bsum[MAXB + 1];
__device__ __align__(16) int   g_erow[MAXE];
__device__ __align__(16) int   g_ecol[MAXE];
__device__ __align__(16) int   g_crow[MAXE];
__device__ __align__(16) float g_cw[MAXE];
__device__ __align__(16) float g_h1[MAXN * F_H];   // x @ W1
__device__ __align__(16) float g_a1[MAXN * F_H];   // relu(conv1)
__device__ __align__(16) float g_h2[MAXN * F_C];   // a1 @ W2

// ---------------------------------------------------------------------------
__global__ void k_zero(int N) {
    int i = blockIdx.x * blockDim.x + threadIdx.x;
    if (i < N) { g_deg[i] = 0.0f; g_hist[i] = 0; }
}

// degrees + per-column histogram; stash row/col (int32 input)
__global__ void k_deg(const int* __restrict__ ei,
                      const float* __restrict__ ew, int E, int N) {
    int e = blockIdx.x * blockDim.x + threadIdx.x;
    if (e >= E) return;
    int r = ei[e];
    int c = ei[E + e];
    g_erow[e] = r;
    g_ecol[e] = c;
    if ((unsigned)r < (unsigned)N && (unsigned)c < (unsigned)N) {
        atomicAdd(&g_deg[c], ew[e]);
        atomicAdd(&g_hist[c], 1);
    }
}

// deg includes self-loop weight 1 -> always > 0
__global__ void k_dinv(int N) {
    int i = blockIdx.x * blockDim.x + threadIdx.x;
    if (i < N) {
        float d = g_deg[i] + 1.0f;
        g_dinv[i] = rsqrtf(d);
    }
}

// ---- hierarchical scan: phase 1 — per-block (1024 elems) totals ----------
__global__ void k_scan1(int N) {
    __shared__ int wsum[8];
    int blk = blockIdx.x, tid = threadIdx.x;
    int lane = tid & 31, wid = tid >> 5;
    int base = blk * SCAN_TILE + tid * 4;
    int t = 0;
    #pragma unroll
    for (int k = 0; k < 4; k++) {
        int i = base + k;
        t += (i < N) ? g_hist[i] : 0;
    }
    #pragma unroll
    for (int o = 16; o > 0; o >>= 1) t += __shfl_xor_sync(0xffffffffu, t, o);
    if (lane == 0) wsum[wid] = t;
    __syncthreads();
    if (tid == 0) {
        int s = 0;
        #pragma unroll
        for (int w = 0; w < 8; w++) s += wsum[w];
        g_bsum[blk] = s;
    }
}

// ---- phase 2 — exclusive scan of block totals (nb <= 256), writes E ------
__global__ void k_scan2(int nb, int N) {
    __shared__ int wsum[8];
    int tid = threadIdx.x, lane = tid & 31, wid = tid >> 5;
    int v = (tid < nb) ? g_bsum[tid] : 0;
    int s = v;
    #pragma unroll
    for (int o = 1; o < 32; o <<= 1) {
        int n = __shfl_up_sync(0xffffffffu, s, o);
        if (lane >= o) s += n;
    }
    if (lane == 31) wsum[wid] = s;
    __syncthreads();
    if (wid == 0 && lane < 8) {
        int w = wsum[lane];
        int ss = w;
        #pragma unroll
        for (int o = 1; o < 8; o <<= 1) {
            int n = __shfl_up_sync(0xffu, ss, o);
            if (lane >= o) ss += n;
        }
        wsum[lane] = ss - w;
    }
    __syncthreads();
    int excl = wsum[wid] + s - v;
    if (tid < nb) g_bsum[tid] = excl;
    if (tid == nb - 1) g_base[N] = excl + v;
}

// ---- phase 3 — local exclusive positions + block offset ------------------
__global__ void k_scan3(int N) {
    __shared__ int wsum[8];
    int blk = blockIdx.x, tid = threadIdx.x;
    int lane = tid & 31, wid = tid >> 5;
    int base = blk * SCAN_TILE + tid * 4;
    int v[4];
    int t = 0;
    #pragma unroll
    for (int k = 0; k < 4; k++) {
        int i = base + k;
        v[k] = (i < N) ? g_hist[i] : 0;
        t += v[k];
    }
    int s = t;
    #pragma unroll
    for (int o = 1; o < 32; o <<= 1) {
        int n = __shfl_up_sync(0xffffffffu, s, o);
        if (lane >= o) s += n;
    }
    if (lane == 31) wsum[wid] = s;
    __syncthreads();
    if (wid == 0 && lane < 8) {
        int w = wsum[lane];
        int ss = w;
        #pragma unroll
        for (int o = 1; o < 8; o <<= 1) {
            int n = __shfl_up_sync(0xffu, ss, o);
            if (lane >= o) ss += n;
        }
        wsum[lane] = ss - w;
    }
    __syncthreads();
    int excl = g_bsum[blk] + wsum[wid] + s - t;
    #pragma unroll
    for (int k = 0; k < 4; k++) {
        int i = base + k;
        if (i < N) { g_base[i] = excl; g_cursor[i] = excl; }
        excl += v[k];
    }
}

// scatter edges into column-sorted CSR; precompute normalized weight
__global__ void k_csr(const float* __restrict__ ew, int E, int N) {
    int e = blockIdx.x * blockDim.x + threadIdx.x;
    if (e >= E) return;
    int r = g_erow[e], c = g_ecol[e];
    if ((unsigned)r >= (unsigned)N || (unsigned)c >= (unsigned)N) return;
    int pos = atomicAdd(&g_cursor[c], 1);
    g_crow[pos] = r;
    g_cw[pos]   = g_dinv[r] * ew[e] * g_dinv[c];
}

// ---------------------------------------------------------------------------
// GEMM1: h1[N,64] = x[N,128] @ W1[128,64].  64-row tile, 2 K-chunks of 64.
__global__ void k_gemm1(const float* __restrict__ x,
                        const float* __restrict__ W1, int N) {
    __shared__ __align__(16) float xs[64][65];     // [r][k] padded
    __shared__ __align__(16) float Ws[64 * 64];    // [k][c] flat
    int tid  = threadIdx.x;          // 256
    int row0 = blockIdx.x * 64;
    int r0 = (tid & 15) * 4;
    int c0 = (tid >> 4) * 4;
    float acc[4][4];
    #pragma unroll
    for (int i = 0; i < 4; i++)
        #pragma unroll
        for (int j = 0; j < 4; j++) acc[i][j] = 0.0f;

    for (int kk = 0; kk < 128; kk += 64) {
        __syncthreads();
        for (int i = tid; i < 1024; i += 256) {
            int k = i >> 4, cc = (i & 15) << 2;
            *(float4*)&Ws[k * 64 + cc] = *(const float4*)&W1[(size_t)(kk + k) * 64 + cc];
        }
        for (int i = tid; i < 1024; i += 256) {
            int r = i >> 4, kc = (i & 15) << 2;
            int row = row0 + r;
            float4 v = make_float4(0.f, 0.f, 0.f, 0.f);
            if (row < N) v = *(const float4*)&x[(size_t)row * 128 + kk + kc];
            xs[r][kc] = v.x; xs[r][kc + 1] = v.y; xs[r][kc + 2] = v.z; xs[r][kc + 3] = v.w;
        }
        __syncthreads();
        #pragma unroll
        for (int k = 0; k < 64; k++) {
            float a0 = xs[r0][k], a1 = xs[r0 + 1][k], a2 = xs[r0 + 2][k], a3 = xs[r0 + 3][k];
            float4 b = *(const float4*)&Ws[k * 64 + c0];
            acc[0][0] += a0 * b.x; acc[0][1] += a0 * b.y; acc[0][2] += a0 * b.z; acc[0][3] += a0 * b.w;
            acc[1][0] += a1 * b.x; acc[1][1] += a1 * b.y; acc[1][2] += a1 * b.z; acc[1][3] += a1 * b.w;
            acc[2][0] += a2 * b.x; acc[2][1] += a2 * b.y; acc[2][2] += a2 * b.z; acc[2][3] += a2 * b.w;
            acc[3][0] += a3 * b.x; acc[3][1] += a3 * b.y; acc[3][2] += a3 * b.z; acc[3][3] += a3 * b.w;
        }
    }
    #pragma unroll
    for (int i = 0; i < 4; i++) {
        int row = row0 + r0 + i;
        if (row < N)
            *(float4*)&g_h1[(size_t)row * 64 + c0] =
                make_float4(acc[i][0], acc[i][1], acc[i][2], acc[i][3]);
    }
}

// agg1: warp per node. acc = b1 + dinv^2*h1[self] + sum_e w*h1[src]; relu.
__global__ void k_agg1(const float* __restrict__ b1, int N) {
    int node = blockIdx.x * (blockDim.x >> 5) + (threadIdx.x >> 5);
    int lane = threadIdx.x & 31;
    if (node >= N) return;
    int s = g_base[node], e = g_base[node + 1];
    float di = g_dinv[node], d2 = di * di;
    const float* hr = &g_h1[(size_t)node * 64];
    float acc0 = b1[lane]      + d2 * hr[lane];
    float acc1 = b1[lane + 32] + d2 * hr[lane + 32];
    if (s < e) {
        int   r = g_crow[s];
        float w = g_cw[s];
        for (int j = s + 1; j < e; j++) {
            int   rn = g_crow[j];
            float wn = g_cw[j];
            const float* p = &g_h1[(size_t)r * 64];
            acc0 += w * p[lane];
            acc1 += w * p[lane + 32];
            r = rn; w = wn;
        }
        const float* p = &g_h1[(size_t)r * 64];
        acc0 += w * p[lane];
        acc1 += w * p[lane + 32];
    }
    g_a1[(size_t)node * 64 + lane]      = fmaxf(acc0, 0.0f);
    g_a1[(size_t)node * 64 + lane + 32] = fmaxf(acc1, 0.0f);
}

// GEMM2: h2[N,40] = a1[N,64] @ W2[64,40]
__global__ void k_gemm2(const float* __restrict__ W2, int N) {
    __shared__ __align__(16) float xs[64][65];
    __shared__ __align__(16) float Ws[64 * 40];
    int tid  = threadIdx.x;          // 256
    int row0 = blockIdx.x * 64;
    for (int i = tid; i < 64 * 40; i += 256) Ws[i] = W2[i];
    for (int i = tid; i < 1024; i += 256) {
        int r = i >> 4, kc = (i & 15) << 2;
        int row = row0 + r;
        float4 v = make_float4(0.f, 0.f, 0.f, 0.f);
        if (row < N) v = *(const float4*)&g_a1[(size_t)row * 64 + kc];
        xs[r][kc] = v.x; xs[r][kc + 1] = v.y; xs[r][kc + 2] = v.z; xs[r][kc + 3] = v.w;
    }
    __syncthreads();
    int r0 = (tid & 31) * 2;         // 64 rows
    int cg = (tid >> 5) * 5;         // 8 groups * 5 = 40 cols
    float acc[2][5];
    #pragma unroll
    for (int i = 0; i < 2; i++)
        #pragma unroll
        for (int j = 0; j < 5; j++) acc[i][j] = 0.0f;
    #pragma unroll
    for (int k = 0; k < 64; k++) {
        float a0 = xs[r0][k], a1 = xs[r0 + 1][k];
        #pragma unroll
        for (int j = 0; j < 5; j++) {
            float b = Ws[k * 40 + cg + j];
            acc[0][j] += a0 * b;
            acc[1][j] += a1 * b;
        }
    }
    #pragma unroll
    for (int i = 0; i < 2; i++) {
        int row = row0 + r0 + i;
        if (row < N) {
            #pragma unroll
            for (int j = 0; j < 5; j++)
                g_h2[(size_t)row * 40 + cg + j] = acc[i][j];
        }
    }
}

// agg2 + log_softmax: warp per node, 40 classes
__global__ void k_agg2(const float* __restrict__ b2, float* __restrict__ out, int N) {
    int node = blockIdx.x * (blockDim.x >> 5) + (threadIdx.x >> 5);
    int lane = threadIdx.x & 31;
    if (node >= N) return;
    int s = g_base[node], e = g_base[node + 1];
    float di = g_dinv[node], d2 = di * di;
    const float* hr = &g_h2[(size_t)node * 40];
    int i2 = 32 + (lane & 7);
    float acc0 = b2[lane] + d2 * hr[lane];
    float acc1 = b2[i2]   + d2 * hr[i2];
    if (s < e) {
        int   r = g_crow[s];
        float w = g_cw[s];
        for (int j = s + 1; j < e; j++) {
            int   rn = g_crow[j];
            float wn = g_cw[j];
            const float* p = &g_h2[(size_t)r * 40];
            acc0 += w * p[lane];
            acc1 += w * p[i2];
            r = rn; w = wn;
        }
        const float* p = &g_h2[(size_t)r * 40];
        acc0 += w * p[lane];
        acc1 += w * p[i2];
    }
    bool hi = lane < 8;
    float m = fmaxf(acc0, hi ? acc1 : -INFINITY);
    #pragma unroll
    for (int o = 16; o > 0; o >>= 1) m = fmaxf(m, __shfl_xor_sync(0xffffffffu, m, o));
    float sum = expf(acc0 - m) + (hi ? expf(acc1 - m) : 0.0f);
    #pragma unroll
    for (int o = 16; o > 0; o >>= 1) sum += __shfl_xor_sync(0xffffffffu, sum, o);
    float lse = m + logf(sum);
    out[(size_t)node * 40 + lane] = acc0 - lse;
    if (hi) out[(size_t)node * 40 + i2] = acc1 - lse;
}

// ---------------------------------------------------------------------------
extern "C" void kernel_launch(void* const* d_in, const int* in_sizes, int n_in,
                              void* d_out, int out_size) {
    const float* x  = (const float*)d_in[0];
    const int*   ei = (const int*)d_in[1];      // int32 [2, E]
    const float* ew = (const float*)d_in[2];
    const float* W1 = (const float*)d_in[3];
    const float* b1 = (const float*)d_in[4];
    const float* W2 = (const float*)d_in[5];
    const float* b2 = (const float*)d_in[6];
    float* out = (float*)d_out;

    int N = in_sizes[0] / F_IN;
    int E = in_sizes[2];
    int nb = (N + SCAN_TILE - 1) / SCAN_TILE;

    k_zero <<<(N + 255) / 256, 256>>>(N);
    k_deg  <<<(E + 255) / 256, 256>>>(ei, ew, E, N);
    k_dinv <<<(N + 255) / 256, 256>>>(N);
    k_scan1<<<nb, 256>>>(N);
    k_scan2<<<1, 256>>>(nb, N);
    k_scan3<<<nb, 256>>>(N);
    k_csr  <<<(E + 255) / 256, 256>>>(ew, E, N);
    k_gemm1<<<(N + 63) / 64, 256>>>(x, W1, N);
    k_agg1 <<<(N + 7) / 8, 256>>>(b1, N);
    k_gemm2<<<(N + 63) / 64, 256>>>(W2, N);
    k_agg2 <<<(N + 7) / 8, 256>>>(b2, out, N);
}

// round 6
// speedup vs baseline: 1.3522x; 1.0889x over previous
#include <cuda_runtime.h>
#include <math.h>

// GCN: N=150000 nodes, E=2,000,000 edges, F=128 -> H=64 -> C=40
// edge_index arrives as int32 [2, E].
// Pipeline:
//   deg/hist -> scan1(+dinv) -> scan2 -> scan3 -> CSR build (packed int2)
//   GEMM1 (x@W1) -> agg1 (CSR gather + self-loop + b1 + ReLU)
//   GEMM2 (a1@W2) -> agg2 (CSR gather + self-loop + b2 + log_softmax) -> out

#define F_IN 128
#define F_H  64
#define F_C  40
#define MAXN 150016
#define MAXE 2000064
#define SCAN_TILE 1024
#define MAXB ((MAXN + SCAN_TILE - 1) / SCAN_TILE)

__device__ __align__(16) float g_deg[MAXN];
__device__ __align__(16) float g_dinv[MAXN];
__device__ __align__(16) int   g_hist[MAXN];
__device__ __align__(16) int   g_base[MAXN + 1];
__device__ __align__(16) int   g_cursor[MAXN];
__device__ __align__(16) int   g_bsum[MAXB + 1];
__device__ __align__(16) int2  g_epack[MAXE];      // {src_row, w_bits}
__device__ __align__(16) float g_h1[MAXN * F_H];   // x @ W1
__device__ __align__(16) float g_a1[MAXN * F_H];   // relu(conv1)
__device__ __align__(16) float g_h2[MAXN * F_C];   // a1 @ W2

// ---------------------------------------------------------------------------
__global__ void k_zero(int N) {
    int i = blockIdx.x * blockDim.x + threadIdx.x;
    if (i < N) { g_deg[i] = 0.0f; g_hist[i] = 0; }
}

// degrees + per-column histogram (int32 input)
__global__ void k_deg(const int* __restrict__ ei,
                      const float* __restrict__ ew, int E, int N) {
    int e = blockIdx.x * blockDim.x + threadIdx.x;
    if (e >= E) return;
    int r = ei[e];
    int c = ei[E + e];
    if ((unsigned)r < (unsigned)N && (unsigned)c < (unsigned)N) {
        atomicAdd(&g_deg[c], ew[e]);
        atomicAdd(&g_hist[c], 1);
    }
}

// ---- scan phase 1 — per-block (1024 elems) totals; dinv fused ------------
__global__ void k_scan1(int N) {
    __shared__ int wsum[8];
    int blk = blockIdx.x, tid = threadIdx.x;
    int lane = tid & 31, wid = tid >> 5;
    int base = blk * SCAN_TILE + tid * 4;
    int t = 0;
    #pragma unroll
    for (int k = 0; k < 4; k++) {
        int i = base + k;
        if (i < N) {
            t += g_hist[i];
            g_dinv[i] = rsqrtf(g_deg[i] + 1.0f);   // self-loop weight 1 -> deg > 0
        }
    }
    #pragma unroll
    for (int o = 16; o > 0; o >>= 1) t += __shfl_xor_sync(0xffffffffu, t, o);
    if (lane == 0) wsum[wid] = t;
    __syncthreads();
    if (tid == 0) {
        int s = 0;
        #pragma unroll
        for (int w = 0; w < 8; w++) s += wsum[w];
        g_bsum[blk] = s;
    }
}

// ---- phase 2 — exclusive scan of block totals (nb <= 256), writes E ------
__global__ void k_scan2(int nb, int N) {
    __shared__ int wsum[8];
    int tid = threadIdx.x, lane = tid & 31, wid = tid >> 5;
    int v = (tid < nb) ? g_bsum[tid] : 0;
    int s = v;
    #pragma unroll
    for (int o = 1; o < 32; o <<= 1) {
        int n = __shfl_up_sync(0xffffffffu, s, o);
        if (lane >= o) s += n;
    }
    if (lane == 31) wsum[wid] = s;
    __syncthreads();
    if (wid == 0 && lane < 8) {
        int w = wsum[lane];
        int ss = w;
        #pragma unroll
        for (int o = 1; o < 8; o <<= 1) {
            int n = __shfl_up_sync(0xffu, ss, o);
            if (lane >= o) ss += n;
        }
        wsum[lane] = ss - w;
    }
    __syncthreads();
    int excl = wsum[wid] + s - v;
    if (tid < nb) g_bsum[tid] = excl;
    if (tid == nb - 1) g_base[N] = excl + v;
}

// ---- phase 3 — local exclusive positions + block offset ------------------
__global__ void k_scan3(int N) {
    __shared__ int wsum[8];
    int blk = blockIdx.x, tid = threadIdx.x;
    int lane = tid & 31, wid = tid >> 5;
    int base = blk * SCAN_TILE + tid * 4;
    int v[4];
    int t = 0;
    #pragma unroll
    for (int k = 0; k < 4; k++) {
        int i = base + k;
        v[k] = (i < N) ? g_hist[i] : 0;
        t += v[k];
    }
    int s = t;
    #pragma unroll
    for (int o = 1; o < 32; o <<= 1) {
        int n = __shfl_up_sync(0xffffffffu, s, o);
        if (lane >= o) s += n;
    }
    if (lane == 31) wsum[wid] = s;
    __syncthreads();
    if (wid == 0 && lane < 8) {
        int w = wsum[lane];
        int ss = w;
        #pragma unroll
        for (int o = 1; o < 8; o <<= 1) {
            int n = __shfl_up_sync(0xffu, ss, o);
            if (lane >= o) ss += n;
        }
        wsum[lane] = ss - w;
    }
    __syncthreads();
    int excl = g_bsum[blk] + wsum[wid] + s - t;
    #pragma unroll
    for (int k = 0; k < 4; k++) {
        int i = base + k;
        if (i < N) { g_base[i] = excl; g_cursor[i] = excl; }
        excl += v[k];
    }
}

// scatter edges into column-sorted CSR (packed int2: {row, weight_bits})
__global__ void k_csr(const int* __restrict__ ei,
                      const float* __restrict__ ew, int E, int N) {
    int e = blockIdx.x * blockDim.x + threadIdx.x;
    if (e >= E) return;
    int r = ei[e], c = ei[E + e];
    if ((unsigned)r >= (unsigned)N || (unsigned)c >= (unsigned)N) return;
    int pos = atomicAdd(&g_cursor[c], 1);
    float w = g_dinv[r] * ew[e] * g_dinv[c];
    g_epack[pos] = make_int2(r, __float_as_int(w));
}

// ---------------------------------------------------------------------------
// GEMM1: h1[N,64] = x[N,128] @ W1[128,64].  64-row tile, 2 K-chunks of 64.
__global__ void k_gemm1(const float* __restrict__ x,
                        const float* __restrict__ W1, int N) {
    __shared__ __align__(16) float xs[64][65];     // [r][k] padded
    __shared__ __align__(16) float Ws[64 * 64];    // [k][c] flat
    int tid  = threadIdx.x;          // 256
    int row0 = blockIdx.x * 64;
    int r0 = (tid & 15) * 4;
    int c0 = (tid >> 4) * 4;
    float acc[4][4];
    #pragma unroll
    for (int i = 0; i < 4; i++)
        #pragma unroll
        for (int j = 0; j < 4; j++) acc[i][j] = 0.0f;

    for (int kk = 0; kk < 128; kk += 64) {
        __syncthreads();
        for (int i = tid; i < 1024; i += 256) {
            int k = i >> 4, cc = (i & 15) << 2;
            *(float4*)&Ws[k * 64 + cc] = *(const float4*)&W1[(size_t)(kk + k) * 64 + cc];
        }
        for (int i = tid; i < 1024; i += 256) {
            int r = i >> 4, kc = (i & 15) << 2;
            int row = row0 + r;
            float4 v = make_float4(0.f, 0.f, 0.f, 0.f);
            if (row < N) v = *(const float4*)&x[(size_t)row * 128 + kk + kc];
            xs[r][kc] = v.x; xs[r][kc + 1] = v.y; xs[r][kc + 2] = v.z; xs[r][kc + 3] = v.w;
        }
        __syncthreads();
        #pragma unroll
        for (int k = 0; k < 64; k++) {
            float a0 = xs[r0][k], a1 = xs[r0 + 1][k], a2 = xs[r0 + 2][k], a3 = xs[r0 + 3][k];
            float4 b = *(const float4*)&Ws[k * 64 + c0];
            acc[0][0] += a0 * b.x; acc[0][1] += a0 * b.y; acc[0][2] += a0 * b.z; acc[0][3] += a0 * b.w;
            acc[1][0] += a1 * b.x; acc[1][1] += a1 * b.y; acc[1][2] += a1 * b.z; acc[1][3] += a1 * b.w;
            acc[2][0] += a2 * b.x; acc[2][1] += a2 * b.y; acc[2][2] += a2 * b.z; acc[2][3] += a2 * b.w;
            acc[3][0] += a3 * b.x; acc[3][1] += a3 * b.y; acc[3][2] += a3 * b.z; acc[3][3] += a3 * b.w;
        }
    }
    #pragma unroll
    for (int i = 0; i < 4; i++) {
        int row = row0 + r0 + i;
        if (row < N)
            *(float4*)&g_h1[(size_t)row * 64 + c0] =
                make_float4(acc[i][0], acc[i][1], acc[i][2], acc[i][3]);
    }
}

// agg1: warp per node. float2 per lane (64 cols = 32 lanes x 2).
__global__ void k_agg1(const float* __restrict__ b1, int N) {
    int node = blockIdx.x * (blockDim.x >> 5) + (threadIdx.x >> 5);
    int lane = threadIdx.x & 31;
    if (node >= N) return;
    int s = g_base[node], e = g_base[node + 1];
    float di = g_dinv[node], d2 = di * di;
    float2 bb   = ((const float2*)b1)[lane];
    float2 self = ((const float2*)&g_h1[(size_t)node * 64])[lane];
    float ax = bb.x + d2 * self.x;
    float ay = bb.y + d2 * self.y;
    if (s < e) {
        int2 pk = g_epack[s];
        for (int j = s + 1; j < e; j++) {
            int2 pn = g_epack[j];
            float w = __int_as_float(pk.y);
            float2 v = ((const float2*)&g_h1[(size_t)pk.x * 64])[lane];
            ax += w * v.x;
            ay += w * v.y;
            pk = pn;
        }
        float w = __int_as_float(pk.y);
        float2 v = ((const float2*)&g_h1[(size_t)pk.x * 64])[lane];
        ax += w * v.x;
        ay += w * v.y;
    }
    ((float2*)&g_a1[(size_t)node * 64])[lane] =
        make_float2(fmaxf(ax, 0.0f), fmaxf(ay, 0.0f));
}

// GEMM2: h2[N,40] = a1[N,64] @ W2[64,40]
__global__ void k_gemm2(const float* __restrict__ W2, int N) {
    __shared__ __align__(16) float xs[64][65];
    __shared__ __align__(16) float Ws[64 * 40];
    int tid  = threadIdx.x;          // 256
    int row0 = blockIdx.x * 64;
    for (int i = tid; i < 64 * 40; i += 256) Ws[i] = W2[i];
    for (int i = tid; i < 1024; i += 256) {
        int r = i >> 4, kc = (i & 15) << 2;
        int row = row0 + r;
        float4 v = make_float4(0.f, 0.f, 0.f, 0.f);
        if (row < N) v = *(const float4*)&g_a1[(size_t)row * 64 + kc];
        xs[r][kc] = v.x; xs[r][kc + 1] = v.y; xs[r][kc + 2] = v.z; xs[r][kc + 3] = v.w;
    }
    __syncthreads();
    int r0 = (tid & 31) * 2;         // 64 rows
    int cg = (tid >> 5) * 5;         // 8 groups * 5 = 40 cols
    float acc[2][5];
    #pragma unroll
    for (int i = 0; i < 2; i++)
        #pragma unroll
        for (int j = 0; j < 5; j++) acc[i][j] = 0.0f;
    #pragma unroll
    for (int k = 0; k < 64; k++) {
        float a0 = xs[r0][k], a1 = xs[r0 + 1][k];
        #pragma unroll
        for (int j = 0; j < 5; j++) {
            float b = Ws[k * 40 + cg + j];
            acc[0][j] += a0 * b;
            acc[1][j] += a1 * b;
        }
    }
    #pragma unroll
    for (int i = 0; i < 2; i++) {
        int row = row0 + r0 + i;
        if (row < N) {
            #pragma unroll
            for (int j = 0; j < 5; j++)
                g_h2[(size_t)row * 40 + cg + j] = acc[i][j];
        }
    }
}

// agg2 + log_softmax: warp per node; lanes 0..19 hold float2 (40 cols).
__global__ void k_agg2(const float* __restrict__ b2, float* __restrict__ out, int N) {
    int node = blockIdx.x * (blockDim.x >> 5) + (threadIdx.x >> 5);
    int lane = threadIdx.x & 31;
    if (node >= N) return;
    int s = g_base[node], e = g_base[node + 1];
    float di = g_dinv[node], d2 = di * di;
    bool act = lane < 20;
    float ax = 0.0f, ay = 0.0f;
    if (act) {
        float2 bb   = ((const float2*)b2)[lane];
        float2 self = ((const float2*)&g_h2[(size_t)node * 40])[lane];
        ax = bb.x + d2 * self.x;
        ay = bb.y + d2 * self.y;
    }
    if (s < e) {
        int2 pk = g_epack[s];
        for (int j = s + 1; j < e; j++) {
            int2 pn = g_epack[j];
            float w = __int_as_float(pk.y);
            // lanes >= 20 read past row end but stay inside g_h2 (MAXN pad)
            float2 v = ((const float2*)&g_h2[(size_t)pk.x * 40])[lane];
            ax += w * v.x;
            ay += w * v.y;
            pk = pn;
        }
        float w = __int_as_float(pk.y);
        float2 v = ((const float2*)&g_h2[(size_t)pk.x * 40])[lane];
        ax += w * v.x;
        ay += w * v.y;
    }
    float m = act ? fmaxf(ax, ay) : -INFINITY;
    #pragma unroll
    for (int o = 16; o > 0; o >>= 1) m = fmaxf(m, __shfl_xor_sync(0xffffffffu, m, o));
    float sum = act ? (expf(ax - m) + expf(ay - m)) : 0.0f;
    #pragma unroll
    for (int o = 16; o > 0; o >>= 1) sum += __shfl_xor_sync(0xffffffffu, sum, o);
    float lse = m + logf(sum);
    if (act)
        ((float2*)&out[(size_t)node * 40])[lane] = make_float2(ax - lse, ay - lse);
}

// ---------------------------------------------------------------------------
extern "C" void kernel_launch(void* const* d_in, const int* in_sizes, int n_in,
                              void* d_out, int out_size) {
    const float* x  = (const float*)d_in[0];
    const int*   ei = (const int*)d_in[1];      // int32 [2, E]
    const float* ew = (const float*)d_in[2];
    const float* W1 = (const float*)d_in[3];
    const float* b1 = (const float*)d_in[4];
    const float* W2 = (const float*)d_in[5];
    const float* b2 = (const float*)d_in[6];
    float* out = (float*)d_out;

    int N = in_sizes[0] / F_IN;
    int E = in_sizes[2];
    int nb = (N + SCAN_TILE - 1) / SCAN_TILE;

    k_zero <<<(N + 255) / 256, 256>>>(N);
    k_deg  <<<(E + 255) / 256, 256>>>(ei, ew, E, N);
    k_scan1<<<nb, 256>>>(N);
    k_scan2<<<1, 256>>>(nb, N);
    k_scan3<<<nb, 256>>>(N);
    k_csr  <<<(E + 255) / 256, 256>>>(ei, ew, E, N);
    k_gemm1<<<(N + 63) / 64, 256>>>(x, W1, N);
    k_agg1 <<<(N + 7) / 8, 256>>>(b1, N);
    k_gemm2<<<(N + 63) / 64, 256>>>(W2, N);
    k_agg2 <<<(N + 7) / 8, 256>>>(b2, out, N);
}

// round 8
// speedup vs baseline: 1.3774x; 1.0186x over previous
#include <cuda_runtime.h>
#include <math.h>

// GCN: N=150000 nodes, E=2,000,000 edges, F=128 -> H=64 -> C=40
// edge_index arrives as int32 [2, E].
// Pipeline (graph-parallel fork/join):
//   stream 0: zero -> deg -> scan1(+dinv) -> scan2 -> scan3 -> csr
//   stream s2: gemm1 (x@W1)                        [independent, overlapped]
//   join ->  agg1 (gather + self-loop + b1 + ReLU)
//        ->  gemm2 (a1@W2) -> agg2 (gather + self-loop + b2 + log_softmax)

#define F_IN 128
#define F_H  64
#define F_C  40
#define MAXN 150016
#define MAXE 2000064
#define SCAN_TILE 1024
#define MAXB ((MAXN + SCAN_TILE - 1) / SCAN_TILE)

__device__ __align__(16) float g_deg[MAXN];
__device__ __align__(16) float g_dinv[MAXN];
__device__ __align__(16) int   g_hist[MAXN];
__device__ __align__(16) int   g_base[MAXN + 1];
__device__ __align__(16) int   g_cursor[MAXN];
__device__ __align__(16) int   g_bsum[MAXB + 1];
__device__ __align__(16) int2  g_epack[MAXE];      // {src_row, w_bits}
__device__ __align__(16) float g_h1[MAXN * F_H];   // x @ W1
__device__ __align__(16) float g_a1[MAXN * F_H];   // relu(conv1)
__device__ __align__(16) float g_h2[MAXN * F_C];   // a1 @ W2

// ---------------------------------------------------------------------------
__global__ void k_zero(int N) {
    int i = blockIdx.x * blockDim.x + threadIdx.x;
    if (i < N) { g_deg[i] = 0.0f; g_hist[i] = 0; }
}

// degrees + per-column histogram (int32 input)
__global__ void k_deg(const int* __restrict__ ei,
                      const float* __restrict__ ew, int E, int N) {
    int e = blockIdx.x * blockDim.x + threadIdx.x;
    if (e >= E) return;
    int r = ei[e];
    int c = ei[E + e];
    if ((unsigned)r < (unsigned)N && (unsigned)c < (unsigned)N) {
        atomicAdd(&g_deg[c], ew[e]);
        atomicAdd(&g_hist[c], 1);
    }
}

// ---- scan phase 1 — per-block (1024 elems) totals; dinv fused ------------
__global__ void k_scan1(int N) {
    __shared__ int wsum[8];
    int blk = blockIdx.x, tid = threadIdx.x;
    int lane = tid & 31, wid = tid >> 5;
    int base = blk * SCAN_TILE + tid * 4;
    int t = 0;
    #pragma unroll
    for (int k = 0; k < 4; k++) {
        int i = base + k;
        if (i < N) {
            t += g_hist[i];
            g_dinv[i] = rsqrtf(g_deg[i] + 1.0f);   // self-loop weight 1 -> deg > 0
        }
    }
    #pragma unroll
    for (int o = 16; o > 0; o >>= 1) t += __shfl_xor_sync(0xffffffffu, t, o);
    if (lane == 0) wsum[wid] = t;
    __syncthreads();
    if (tid == 0) {
        int s = 0;
        #pragma unroll
        for (int w = 0; w < 8; w++) s += wsum[w];
        g_bsum[blk] = s;
    }
}

// ---- phase 2 — exclusive scan of block totals (nb <= 256), writes E ------
__global__ void k_scan2(int nb, int N) {
    __shared__ int wsum[8];
    int tid = threadIdx.x, lane = tid & 31, wid = tid >> 5;
    int v = (tid < nb) ? g_bsum[tid] : 0;
    int s = v;
    #pragma unroll
    for (int o = 1; o < 32; o <<= 1) {
        int n = __shfl_up_sync(0xffffffffu, s, o);
        if (lane >= o) s += n;
    }
    if (lane == 31) wsum[wid] = s;
    __syncthreads();
    if (wid == 0 && lane < 8) {
        int w = wsum[lane];
        int ss = w;
        #pragma unroll
        for (int o = 1; o < 8; o <<= 1) {
            int n = __shfl_up_sync(0xffu, ss, o);
            if (lane >= o) ss += n;
        }
        wsum[lane] = ss - w;
    }
    __syncthreads();
    int excl = wsum[wid] + s - v;
    if (tid < nb) g_bsum[tid] = excl;
    if (tid == nb - 1) g_base[N] = excl + v;
}

// ---- phase 3 — local exclusive positions + block offset ------------------
__global__ void k_scan3(int N) {
    __shared__ int wsum[8];
    int blk = blockIdx.x, tid = threadIdx.x;
    int lane = tid & 31, wid = tid >> 5;
    int base = blk * SCAN_TILE + tid * 4;
    int v[4];
    int t = 0;
    #pragma unroll
    for (int k = 0; k < 4; k++) {
        int i = base + k;
        v[k] = (i < N) ? g_hist[i] : 0;
        t += v[k];
    }
    int s = t;
    #pragma unroll
    for (int o = 1; o < 32; o <<= 1) {
        int n = __shfl_up_sync(0xffffffffu, s, o);
        if (lane >= o) s += n;
    }
    if (lane == 31) wsum[wid] = s;
    __syncthreads();
    if (wid == 0 && lane < 8) {
        int w = wsum[lane];
        int ss = w;
        #pragma unroll
        for (int o = 1; o < 8; o <<= 1) {
            int n = __shfl_up_sync(0xffu, ss, o);
            if (lane >= o) ss += n;
        }
        wsum[lane] = ss - w;
    }
    __syncthreads();
    int excl = g_bsum[blk] + wsum[wid] + s - t;
    #pragma unroll
    for (int k = 0; k < 4; k++) {
        int i = base + k;
        if (i < N) { g_base[i] = excl; g_cursor[i] = excl; }
        excl += v[k];
    }
}

// scatter edges into column-sorted CSR (packed int2: {row, weight_bits})
__global__ void k_csr(const int* __restrict__ ei,
                      const float* __restrict__ ew, int E, int N) {
    int e = blockIdx.x * blockDim.x + threadIdx.x;
    if (e >= E) return;
    int r = ei[e], c = ei[E + e];
    if ((unsigned)r >= (unsigned)N || (unsigned)c >= (unsigned)N) return;
    int pos = atomicAdd(&g_cursor[c], 1);
    float w = g_dinv[r] * ew[e] * g_dinv[c];
    g_epack[pos] = make_int2(r, __float_as_int(w));
}

// ---------------------------------------------------------------------------
// GEMM1: h1[N,64] = x[N,128] @ W1[128,64].  64-row tile, 2 K-chunks of 64.
__global__ void k_gemm1(const float* __restrict__ x,
                        const float* __restrict__ W1, int N) {
    __shared__ __align__(16) float xs[64][65];     // [r][k] padded
    __shared__ __align__(16) float Ws[64 * 64];    // [k][c] flat
    int tid  = threadIdx.x;          // 256
    int row0 = blockIdx.x * 64;
    int r0 = (tid & 15) * 4;
    int c0 = (tid >> 4) * 4;
    float acc[4][4];
    #pragma unroll
    for (int i = 0; i < 4; i++)
        #pragma unroll
        for (int j = 0; j < 4; j++) acc[i][j] = 0.0f;

    for (int kk = 0; kk < 128; kk += 64) {
        __syncthreads();
        for (int i = tid; i < 1024; i += 256) {
            int k = i >> 4, cc = (i & 15) << 2;
            *(float4*)&Ws[k * 64 + cc] = *(const float4*)&W1[(size_t)(kk + k) * 64 + cc];
        }
        for (int i = tid; i < 1024; i += 256) {
            int r = i >> 4, kc = (i & 15) << 2;
            int row = row0 + r;
            float4 v = make_float4(0.f, 0.f, 0.f, 0.f);
            if (row < N) v = *(const float4*)&x[(size_t)row * 128 + kk + kc];
            xs[r][kc] = v.x; xs[r][kc + 1] = v.y; xs[r][kc + 2] = v.z; xs[r][kc + 3] = v.w;
        }
        __syncthreads();
        #pragma unroll
        for (int k = 0; k < 64; k++) {
            float a0 = xs[r0][k], a1 = xs[r0 + 1][k], a2 = xs[r0 + 2][k], a3 = xs[r0 + 3][k];
            float4 b = *(const float4*)&Ws[k * 64 + c0];
            acc[0][0] += a0 * b.x; acc[0][1] += a0 * b.y; acc[0][2] += a0 * b.z; acc[0][3] += a0 * b.w;
            acc[1][0] += a1 * b.x; acc[1][1] += a1 * b.y; acc[1][2] += a1 * b.z; acc[1][3] += a1 * b.w;
            acc[2][0] += a2 * b.x; acc[2][1] += a2 * b.y; acc[2][2] += a2 * b.z; acc[2][3] += a2 * b.w;
            acc[3][0] += a3 * b.x; acc[3][1] += a3 * b.y; acc[3][2] += a3 * b.z; acc[3][3] += a3 * b.w;
        }
    }
    #pragma unroll
    for (int i = 0; i < 4; i++) {
        int row = row0 + r0 + i;
        if (row < N)
            *(float4*)&g_h1[(size_t)row * 64 + c0] =
                make_float4(acc[i][0], acc[i][1], acc[i][2], acc[i][3]);
    }
}

// agg1: warp per node. float2 per lane (64 cols = 32 lanes x 2).
__global__ void k_agg1(const float* __restrict__ b1, int N) {
    int node = blockIdx.x * (blockDim.x >> 5) + (threadIdx.x >> 5);
    int lane = threadIdx.x & 31;
    if (node >= N) return;
    int s = g_base[node], e = g_base[node + 1];
    float di = g_dinv[node], d2 = di * di;
    float2 bb   = ((const float2*)b1)[lane];
    float2 self = ((const float2*)&g_h1[(size_t)node * 64])[lane];
    float ax = bb.x + d2 * self.x;
    float ay = bb.y + d2 * self.y;
    if (s < e) {
        int2 pk = g_epack[s];
        for (int j = s + 1; j < e; j++) {
            int2 pn = g_epack[j];
            float w = __int_as_float(pk.y);
            float2 v = ((const float2*)&g_h1[(size_t)pk.x * 64])[lane];
            ax += w * v.x;
            ay += w * v.y;
            pk = pn;
        }
        float w = __int_as_float(pk.y);
        float2 v = ((const float2*)&g_h1[(size_t)pk.x * 64])[lane];
        ax += w * v.x;
        ay += w * v.y;
    }
    ((float2*)&g_a1[(size_t)node * 64])[lane] =
        make_float2(fmaxf(ax, 0.0f), fmaxf(ay, 0.0f));
}

// GEMM2: h2[N,40] = a1[N,64] @ W2[64,40]
__global__ void k_gemm2(const float* __restrict__ W2, int N) {
    __shared__ __align__(16) float xs[64][65];
    __shared__ __align__(16) float Ws[64 * 40];
    int tid  = threadIdx.x;          // 256
    int row0 = blockIdx.x * 64;
    for (int i = tid; i < 64 * 40; i += 256) Ws[i] = W2[i];
    for (int i = tid; i < 1024; i += 256) {
        int r = i >> 4, kc = (i & 15) << 2;
        int row = row0 + r;
        float4 v = make_float4(0.f, 0.f, 0.f, 0.f);
        if (row < N) v = *(const float4*)&g_a1[(size_t)row * 64 + kc];
        xs[r][kc] = v.x; xs[r][kc + 1] = v.y; xs[r][kc + 2] = v.z; xs[r][kc + 3] = v.w;
    }
    __syncthreads();
    int r0 = (tid & 31) * 2;         // 64 rows
    int cg = (tid >> 5) * 5;         // 8 groups * 5 = 40 cols
    float acc[2][5];
    #pragma unroll
    for (int i = 0; i < 2; i++)
        #pragma unroll
        for (int j = 0; j < 5; j++) acc[i][j] = 0.0f;
    #pragma unroll
    for (int k = 0; k < 64; k++) {
        float a0 = xs[r0][k], a1 = xs[r0 + 1][k];
        #pragma unroll
        for (int j = 0; j < 5; j++) {
            float b = Ws[k * 40 + cg + j];
            acc[0][j] += a0 * b;
            acc[1][j] += a1 * b;
        }
    }
    #pragma unroll
    for (int i = 0; i < 2; i++) {
        int row = row0 + r0 + i;
        if (row < N) {
            #pragma unroll
            for (int j = 0; j < 5; j++)
                g_h2[(size_t)row * 40 + cg + j] = acc[i][j];
        }
    }
}

// agg2 + log_softmax: warp per node; lanes 0..19 hold float2 (40 cols).
__global__ void k_agg2(const float* __restrict__ b2, float* __restrict__ out, int N) {
    int node = blockIdx.x * (blockDim.x >> 5) + (threadIdx.x >> 5);
    int lane = threadIdx.x & 31;
    if (node >= N) return;
    int s = g_base[node], e = g_base[node + 1];
    float di = g_dinv[node], d2 = di * di;
    bool act = lane < 20;
    float ax = 0.0f, ay = 0.0f;
    if (act) {
        float2 bb   = ((const float2*)b2)[lane];
        float2 self = ((const float2*)&g_h2[(size_t)node * 40])[lane];
        ax = bb.x + d2 * self.x;
        ay = bb.y + d2 * self.y;
    }
    if (s < e) {
        int2 pk = g_epack[s];
        for (int j = s + 1; j < e; j++) {
            int2 pn = g_epack[j];
            float w = __int_as_float(pk.y);
            // lanes >= 20 read past row end but stay inside g_h2 (MAXN pad)
            float2 v = ((const float2*)&g_h2[(size_t)pk.x * 40])[lane];
            ax += w * v.x;
            ay += w * v.y;
            pk = pn;
        }
        float w = __int_as_float(pk.y);
        float2 v = ((const float2*)&g_h2[(size_t)pk.x * 40])[lane];
        ax += w * v.x;
        ay += w * v.y;
    }
    float m = act ? fmaxf(ax, ay) : -INFINITY;
    #pragma unroll
    for (int o = 16; o > 0; o >>= 1) m = fmaxf(m, __shfl_xor_sync(0xffffffffu, m, o));
    float sum = act ? (expf(ax - m) + expf(ay - m)) : 0.0f;
    #pragma unroll
    for (int o = 16; o > 0; o >>= 1) sum += __shfl_xor_sync(0xffffffffu, sum, o);
    float lse = m + logf(sum);
    if (act)
        ((float2*)&out[(size_t)node * 40])[lane] = make_float2(ax - lse, ay - lse);
}

// ---------------------------------------------------------------------------
extern "C" void kernel_launch(void* const* d_in, const int* in_sizes, int n_in,
                              void* d_out, int out_size) {
    const float* x  = (const float*)d_in[0];
    const int*   ei = (const int*)d_in[1];      // int32 [2, E]
    const float* ew = (const float*)d_in[2];
    const float* W1 = (const float*)d_in[3];
    const float* b1 = (const float*)d_in[4];
    const float* W2 = (const float*)d_in[5];
    const float* b2 = (const float*)d_in[6];
    float* out = (float*)d_out;

    int N = in_sizes[0] / F_IN;
    int E = in_sizes[2];
    int nb = (N + SCAN_TILE - 1) / SCAN_TILE;

    // Lazily created host-side resources (first call happens before graph
    // capture; creation is host state only — captured device work is
    // identical on every call).
    static cudaStream_t s2 = nullptr;
    static cudaEvent_t ev_fork = nullptr, ev_join = nullptr;
    if (s2 == nullptr) {
        cudaStreamCreateWithFlags(&s2, cudaStreamNonBlocking);
        cudaEventCreateWithFlags(&ev_fork, cudaEventDisableTiming);
        cudaEventCreateWithFlags(&ev_join, cudaEventDisableTiming);
    }

    // Fork: GEMM1 (depends only on x, W1) runs concurrently with CSR build.
    cudaEventRecord(ev_fork, 0);
    cudaStreamWaitEvent(s2, ev_fork, 0);
    k_gemm1<<<(N + 63) / 64, 256, 0, s2>>>(x, W1, N);
    cudaEventRecord(ev_join, s2);

    // Main stream: CSR construction chain.
    k_zero <<<(N + 255) / 256, 256>>>(N);
    k_deg  <<<(E + 255) / 256, 256>>>(ei, ew, E, N);
    k_scan1<<<nb, 256>>>(N);
    k_scan2<<<1, 256>>>(nb, N);
    k_scan3<<<nb, 256>>>(N);
    k_csr  <<<(E + 255) / 256, 256>>>(ei, ew, E, N);

    // Join: agg1 needs both h1 (s2) and CSR (stream 0).
    cudaStreamWaitEvent(0, ev_join, 0);
    k_agg1 <<<(N + 7) / 8, 256>>>(b1, N);
    k_gemm2<<<(N + 63) / 64, 256>>>(W2, N);
    k_agg2 <<<(N + 7) / 8, 256>>>(b2, out, N);
}

// round 10
// speedup vs baseline: 1.3887x; 1.0082x over previous
#include <cuda_runtime.h>
#include <math.h>

// GCN: N=150000 nodes, E=2,000,000 edges, F=128 -> H=64 -> C=40
// edge_index arrives as int32 [2, E].
// Pipeline (graph-parallel fork/join):
//   stream 0: zero -> deg -> scan1(+dinv) -> scan2 -> scan3 -> csr
//   stream s2: gemm1 (x@W1)                        [independent, overlapped]
//   join ->  agg1 (gather + self-loop + b1 + ReLU)
//        ->  gemm2 (a1@W2) -> agg2 (gather + self-loop + b2 + log_softmax)

#define F_IN 128
#define F_H  64
#define F_C  40
#define MAXN 150016
#define MAXE 2000064
#define SCAN_TILE 1024
#define MAXB ((MAXN + SCAN_TILE - 1) / SCAN_TILE)

__device__ __align__(16) float g_deg[MAXN];
__device__ __align__(16) float g_dinv[MAXN];
__device__ __align__(16) int   g_hist[MAXN];
__device__ __align__(16) int   g_base[MAXN + 1];
__device__ __align__(16) int   g_cursor[MAXN];
__device__ __align__(16) int   g_bsum[MAXB + 1];
__device__ __align__(16) int2  g_epack[MAXE];      // {src_row, w_bits}
__device__ __align__(16) float g_h1[MAXN * F_H];   // x @ W1
__device__ __align__(16) float g_a1[MAXN * F_H];   // relu(conv1)
__device__ __align__(16) float g_h2[MAXN * F_C];   // a1 @ W2

// ---------------------------------------------------------------------------
__global__ void k_zero(int N) {
    int i = blockIdx.x * blockDim.x + threadIdx.x;
    if (i < N) { g_deg[i] = 0.0f; g_hist[i] = 0; }
}

// degrees + per-column histogram (int32 input)
__global__ void k_deg(const int* __restrict__ ei,
                      const float* __restrict__ ew, int E, int N) {
    int e = blockIdx.x * blockDim.x + threadIdx.x;
    if (e >= E) return;
    int r = ei[e];
    int c = ei[E + e];
    if ((unsigned)r < (unsigned)N && (unsigned)c < (unsigned)N) {
        atomicAdd(&g_deg[c], ew[e]);
        atomicAdd(&g_hist[c], 1);
    }
}

// ---- scan phase 1 — per-block (1024 elems) totals; dinv fused ------------
__global__ void k_scan1(int N) {
    __shared__ int wsum[8];
    int blk = blockIdx.x, tid = threadIdx.x;
    int lane = tid & 31, wid = tid >> 5;
    int base = blk * SCAN_TILE + tid * 4;
    int t = 0;
    #pragma unroll
    for (int k = 0; k < 4; k++) {
        int i = base + k;
        if (i < N) {
            t += g_hist[i];
            g_dinv[i] = rsqrtf(g_deg[i] + 1.0f);   // self-loop weight 1 -> deg > 0
        }
    }
    #pragma unroll
    for (int o = 16; o > 0; o >>= 1) t += __shfl_xor_sync(0xffffffffu, t, o);
    if (lane == 0) wsum[wid] = t;
    __syncthreads();
    if (tid == 0) {
        int s = 0;
        #pragma unroll
        for (int w = 0; w < 8; w++) s += wsum[w];
        g_bsum[blk] = s;
    }
}

// ---- phase 2 — exclusive scan of block totals (nb <= 256), writes E ------
__global__ void k_scan2(int nb, int N) {
    __shared__ int wsum[8];
    int tid = threadIdx.x, lane = tid & 31, wid = tid >> 5;
    int v = (tid < nb) ? g_bsum[tid] : 0;
    int s = v;
    #pragma unroll
    for (int o = 1; o < 32; o <<= 1) {
        int n = __shfl_up_sync(0xffffffffu, s, o);
        if (lane >= o) s += n;
    }
    if (lane == 31) wsum[wid] = s;
    __syncthreads();
    if (wid == 0 && lane < 8) {
        int w = wsum[lane];
        int ss = w;
        #pragma unroll
        for (int o = 1; o < 8; o <<= 1) {
            int n = __shfl_up_sync(0xffu, ss, o);
            if (lane >= o) ss += n;
        }
        wsum[lane] = ss - w;
    }
    __syncthreads();
    int excl = wsum[wid] + s - v;
    if (tid < nb) g_bsum[tid] = excl;
    if (tid == nb - 1) g_base[N] = excl + v;
}

// ---- phase 3 — local exclusive positions + block offset ------------------
__global__ void k_scan3(int N) {
    __shared__ int wsum[8];
    int blk = blockIdx.x, tid = threadIdx.x;
    int lane = tid & 31, wid = tid >> 5;
    int base = blk * SCAN_TILE + tid * 4;
    int v[4];
    int t = 0;
    #pragma unroll
    for (int k = 0; k < 4; k++) {
        int i = base + k;
        v[k] = (i < N) ? g_hist[i] : 0;
        t += v[k];
    }
    int s = t;
    #pragma unroll
    for (int o = 1; o < 32; o <<= 1) {
        int n = __shfl_up_sync(0xffffffffu, s, o);
        if (lane >= o) s += n;
    }
    if (lane == 31) wsum[wid] = s;
    __syncthreads();
    if (wid == 0 && lane < 8) {
        int w = wsum[lane];
        int ss = w;
        #pragma unroll
        for (int o = 1; o < 8; o <<= 1) {
            int n = __shfl_up_sync(0xffu, ss, o);
            if (lane >= o) ss += n;
        }
        wsum[lane] = ss - w;
    }
    __syncthreads();
    int excl = g_bsum[blk] + wsum[wid] + s - t;
    #pragma unroll
    for (int k = 0; k < 4; k++) {
        int i = base + k;
        if (i < N) { g_base[i] = excl; g_cursor[i] = excl; }
        excl += v[k];
    }
}

// scatter edges into column-sorted CSR (packed int2: {row, weight_bits})
__global__ void k_csr(const int* __restrict__ ei,
                      const float* __restrict__ ew, int E, int N) {
    int e = blockIdx.x * blockDim.x + threadIdx.x;
    if (e >= E) return;
    int r = ei[e], c = ei[E + e];
    if ((unsigned)r >= (unsigned)N || (unsigned)c >= (unsigned)N) return;
    int pos = atomicAdd(&g_cursor[c], 1);
    float w = g_dinv[r] * ew[e] * g_dinv[c];
    g_epack[pos] = make_int2(r, __float_as_int(w));
}

// ---------------------------------------------------------------------------
// GEMM1: h1[N,64] = x[N,128] @ W1[128,64].  64-row tile, 2 K-chunks of 64.
__global__ void k_gemm1(const float* __restrict__ x,
                        const float* __restrict__ W1, int N) {
    __shared__ __align__(16) float xs[64][65];     // [r][k] padded
    __shared__ __align__(16) float Ws[64 * 64];    // [k][c] flat
    int tid  = threadIdx.x;          // 256
    int row0 = blockIdx.x * 64;
    int r0 = (tid & 15) * 4;
    int c0 = (tid >> 4) * 4;
    float acc[4][4];
    #pragma unroll
    for (int i = 0; i < 4; i++)
        #pragma unroll
        for (int j = 0; j < 4; j++) acc[i][j] = 0.0f;

    for (int kk = 0; kk < 128; kk += 64) {
        __syncthreads();
        for (int i = tid; i < 1024; i += 256) {
            int k = i >> 4, cc = (i & 15) << 2;
            *(float4*)&Ws[k * 64 + cc] = *(const float4*)&W1[(size_t)(kk + k) * 64 + cc];
        }
        for (int i = tid; i < 1024; i += 256) {
            int r = i >> 4, kc = (i & 15) << 2;
            int row = row0 + r;
            float4 v = make_float4(0.f, 0.f, 0.f, 0.f);
            if (row < N) v = *(const float4*)&x[(size_t)row * 128 + kk + kc];
            xs[r][kc] = v.x; xs[r][kc + 1] = v.y; xs[r][kc + 2] = v.z; xs[r][kc + 3] = v.w;
        }
        __syncthreads();
        #pragma unroll
        for (int k = 0; k < 64; k++) {
            float a0 = xs[r0][k], a1 = xs[r0 + 1][k], a2 = xs[r0 + 2][k], a3 = xs[r0 + 3][k];
            float4 b = *(const float4*)&Ws[k * 64 + c0];
            acc[0][0] += a0 * b.x; acc[0][1] += a0 * b.y; acc[0][2] += a0 * b.z; acc[0][3] += a0 * b.w;
            acc[1][0] += a1 * b.x; acc[1][1] += a1 * b.y; acc[1][2] += a1 * b.z; acc[1][3] += a1 * b.w;
            acc[2][0] += a2 * b.x; acc[2][1] += a2 * b.y; acc[2][2] += a2 * b.z; acc[2][3] += a2 * b.w;
            acc[3][0] += a3 * b.x; acc[3][1] += a3 * b.y; acc[3][2] += a3 * b.z; acc[3][3] += a3 * b.w;
        }
    }
    #pragma unroll
    for (int i = 0; i < 4; i++) {
        int row = row0 + r0 + i;
        if (row < N)
            *(float4*)&g_h1[(size_t)row * 64 + c0] =
                make_float4(acc[i][0], acc[i][1], acc[i][2], acc[i][3]);
    }
}

// agg1: warp per node. float2 per lane (64 cols = 32 lanes x 2).
__global__ void k_agg1(const float* __restrict__ b1, int N) {
    int node = blockIdx.x * (blockDim.x >> 5) + (threadIdx.x >> 5);
    int lane = threadIdx.x & 31;
    if (node >= N) return;
    int s = g_base[node], e = g_base[node + 1];
    float di = g_dinv[node], d2 = di * di;
    float2 bb   = ((const float2*)b1)[lane];
    float2 self = ((const float2*)&g_h1[(size_t)node * 64])[lane];
    float ax = bb.x + d2 * self.x;
    float ay = bb.y + d2 * self.y;
    if (s < e) {
        int2 pk = g_epack[s];
        for (int j = s + 1; j < e; j++) {
            int2 pn = g_epack[j];
            float w = __int_as_float(pk.y);
            float2 v = ((const float2*)&g_h1[(size_t)pk.x * 64])[lane];
            ax += w * v.x;
            ay += w * v.y;
            pk = pn;
        }
        float w = __int_as_float(pk.y);
        float2 v = ((const float2*)&g_h1[(size_t)pk.x * 64])[lane];
        ax += w * v.x;
        ay += w * v.y;
    }
    ((float2*)&g_a1[(size_t)node * 64])[lane] =
        make_float2(fmaxf(ax, 0.0f), fmaxf(ay, 0.0f));
}

// GEMM2: h2[N,40] = a1[N,64] @ W2[64,40]
__global__ void k_gemm2(const float* __restrict__ W2, int N) {
    __shared__ __align__(16) float xs[64][65];
    __shared__ __align__(16) float Ws[64 * 40];
    int tid  = threadIdx.x;          // 256
    int row0 = blockIdx.x * 64;
    for (int i = tid; i < 64 * 40; i += 256) Ws[i] = W2[i];
    for (int i = tid; i < 1024; i += 256) {
        int r = i >> 4, kc = (i & 15) << 2;
        int row = row0 + r;
        float4 v = make_float4(0.f, 0.f, 0.f, 0.f);
        if (row < N) v = *(const float4*)&g_a1[(size_t)row * 64 + kc];
        xs[r][kc] = v.x; xs[r][kc + 1] = v.y; xs[r][kc + 2] = v.z; xs[r][kc + 3] = v.w;
    }
    __syncthreads();
    int r0 = (tid & 31) * 2;         // 64 rows
    int cg = (tid >> 5) * 5;         // 8 groups * 5 = 40 cols
    float acc[2][5];
    #pragma unroll
    for (int i = 0; i < 2; i++)
        #pragma unroll
        for (int j = 0; j < 5; j++) acc[i][j] = 0.0f;
    #pragma unroll
    for (int k = 0; k < 64; k++) {
        float a0 = xs[r0][k], a1 = xs[r0 + 1][k];
        #pragma unroll
        for (int j = 0; j < 5; j++) {
            float b = Ws[k * 40 + cg + j];
            acc[0][j] += a0 * b;
            acc[1][j] += a1 * b;
        }
    }
    #pragma unroll
    for (int i = 0; i < 2; i++) {
        int row = row0 + r0 + i;
        if (row < N) {
            #pragma unroll
            for (int j = 0; j < 5; j++)
                g_h2[(size_t)row * 40 + cg + j] = acc[i][j];
        }
    }
}

// agg2 + log_softmax: warp per node; lanes 0..19 hold float2 (40 cols).
__global__ void k_agg2(const float* __restrict__ b2, float* __restrict__ out, int N) {
    int node = blockIdx.x * (blockDim.x >> 5) + (threadIdx.x >> 5);
    int lane = threadIdx.x & 31;
    if (node >= N) return;
    int s = g_base[node], e = g_base[node + 1];
    float di = g_dinv[node], d2 = di * di;
    bool act = lane < 20;
    float ax = 0.0f, ay = 0.0f;
    if (act) {
        float2 bb   = ((const float2*)b2)[lane];
        float2 self = ((const float2*)&g_h2[(size_t)node * 40])[lane];
        ax = bb.x + d2 * self.x;
        ay = bb.y + d2 * self.y;
    }
    if (s < e) {
        int2 pk = g_epack[s];
        for (int j = s + 1; j < e; j++) {
            int2 pn = g_epack[j];
            float w = __int_as_float(pk.y);
            // lanes >= 20 read past row end but stay inside g_h2 (MAXN pad)
            float2 v = ((const float2*)&g_h2[(size_t)pk.x * 40])[lane];
            ax += w * v.x;
            ay += w * v.y;
            pk = pn;
        }
        float w = __int_as_float(pk.y);
        float2 v = ((const float2*)&g_h2[(size_t)pk.x * 40])[lane];
        ax += w * v.x;
        ay += w * v.y;
    }
    float m = act ? fmaxf(ax, ay) : -INFINITY;
    #pragma unroll
    for (int o = 16; o > 0; o >>= 1) m = fmaxf(m, __shfl_xor_sync(0xffffffffu, m, o));
    float sum = act ? (expf(ax - m) + expf(ay - m)) : 0.0f;
    #pragma unroll
    for (int o = 16; o > 0; o >>= 1) sum += __shfl_xor_sync(0xffffffffu, sum, o);
    float lse = m + logf(sum);
    if (act)
        ((float2*)&out[(size_t)node * 40])[lane] = make_float2(ax - lse, ay - lse);
}

// ---------------------------------------------------------------------------
extern "C" void kernel_launch(void* const* d_in, const int* in_sizes, int n_in,
                              void* d_out, int out_size) {
    const float* x  = (const float*)d_in[0];
    const int*   ei = (const int*)d_in[1];      // int32 [2, E]
    const float* ew = (const float*)d_in[2];
    const float* W1 = (const float*)d_in[3];
    const float* b1 = (const float*)d_in[4];
    const float* W2 = (const float*)d_in[5];
    const float* b2 = (const float*)d_in[6];
    float* out = (float*)d_out;

    int N = in_sizes[0] / F_IN;
    int E = in_sizes[2];
    int nb = (N + SCAN_TILE - 1) / SCAN_TILE;

    // Lazily created host-side resources (first call happens before graph
    // capture; creation is host state only — captured device work is
    // identical on every call).
    static cudaStream_t s2 = nullptr;
    static cudaEvent_t ev_fork = nullptr, ev_join = nullptr;
    if (s2 == nullptr) {
        cudaStreamCreateWithFlags(&s2, cudaStreamNonBlocking);
        cudaEventCreateWithFlags(&ev_fork, cudaEventDisableTiming);
        cudaEventCreateWithFlags(&ev_join, cudaEventDisableTiming);
    }

    // Fork: GEMM1 (depends only on x, W1) runs concurrently with CSR build.
    cudaEventRecord(ev_fork, 0);
    cudaStreamWaitEvent(s2, ev_fork, 0);
    k_gemm1<<<(N + 63) / 64, 256, 0, s2>>>(x, W1, N);
    cudaEventRecord(ev_join, s2);

    // Main stream: CSR construction chain.
    k_zero <<<(N + 255) / 256, 256>>>(N);
    k_deg  <<<(E + 255) / 256, 256>>>(ei, ew, E, N);
    k_scan1<<<nb, 256>>>(N);
    k_scan2<<<1, 256>>>(nb, N);
    k_scan3<<<nb, 256>>>(N);
    k_csr  <<<(E + 255) / 256, 256>>>(ei, ew, E, N);

    // Join: agg1 needs both h1 (s2) and CSR (stream 0).
    cudaStreamWaitEvent(0, ev_join, 0);
    k_agg1 <<<(N + 7) / 8, 256>>>(b1, N);
    k_gemm2<<<(N + 63) / 64, 256>>>(W2, N);
    k_agg2 <<<(N + 7) / 8, 256>>>(b2, out, N);
}